// round 5
// baseline (speedup 1.0000x reference)
#include <cuda_runtime.h>
#include <math.h>

// ---------------------------------------------------------------------------
// casConv2d: B=1, C=128, H=W=32, OC=128, K=3, pad=1 -> OH=OW=32, L=1024
// 36 real chunks of 32 ckk-terms; front-pad chunk is exactly zero after quant.
//
// Kernel 1: per-chunk partial sums -> g_part[l][j][oc]   (fp32, 18.9 MB)
// Kernel 2: block-per-l: totals(+bias) -> scale/zp -> fake-quant -> out
// 3 noop launches pad the stream so ncu's (-s 5 -c 1) window hits k_partials.
// ---------------------------------------------------------------------------

#define WSTR 130  // w_s row stride (floats)

typedef unsigned long long u64;

__device__ float g_part[1024u * 36u * 128u];  // [l][j][oc]

__device__ __forceinline__ u64 fma2(u64 a, u64 b, u64 c) {
    u64 d;
    asm("fma.rn.f32x2 %0, %1, %2, %3;" : "=l"(d) : "l"(a), "l"(b), "l"(c));
    return d;
}

__device__ __forceinline__ u64 bcast2(float v) {
    u64 d;
    unsigned u = __float_as_uint(v);
    asm("mov.b64 %0, {%1, %1};" : "=l"(d) : "r"(u));
    return d;
}

__device__ __forceinline__ float2 unpack2(u64 v) {
    float2 f;
    asm("mov.b64 {%0, %1}, %2;" : "=f"(f.x), "=f"(f.y) : "l"(v));
    return f;
}

// ---------------------------------------------------------------------------
// Kernel 1 (UNCHANGED from R4 — being profiled this round).
// grid = (16 l-tiles, 36 chunks), block = 256.
// ---------------------------------------------------------------------------
__global__ void __launch_bounds__(256)
k_partials(const float* __restrict__ x, const float* __restrict__ w) {
    __shared__ float x_s[5 * 4 * 34];
    __shared__ float w_s[32 * WSTR];
    __shared__ int   xoff_s[32];

    const int j    = blockIdx.y;
    const int oh0  = blockIdx.x * 2;
    const int base = 32 * j;
    const int cmin = base / 9;
    const int r0   = base - 9 * cmin;
    const int tid  = threadIdx.x;

    if (tid < 32) {
        int idx9 = r0 + tid;
        int cr   = idx9 / 9;
        int rem  = idx9 - cr * 9;
        int kh   = rem / 3;
        int kw   = rem - kh * 3;
        xoff_s[tid] = cr * 136 + kh * 34 + kw;
    }

    for (int e = tid; e < 5 * 4 * 34; e += 256) {
        int cr  = e / 136;
        int rem = e - cr * 136;
        int rr  = rem / 34;
        int cc  = rem - rr * 34;
        int c   = cmin + cr;
        int gh  = oh0 - 1 + rr;
        int gw  = cc - 1;
        float v = 0.0f;
        if (c < 128 && (unsigned)gh < 32u && (unsigned)gw < 32u)
            v = x[(c << 10) + (gh << 5) + gw];
        x_s[e] = v;
    }
    for (int e = tid; e < 4096; e += 256) {
        int oc = e >> 5;
        int m  = e & 31;
        w_s[m * WSTR + oc] = w[oc * 1152 + base + m];
    }
    __syncthreads();

    const int lcol = tid & 15;
    const int oc0  = (tid >> 4) << 3;
    const int lrow = lcol >> 3;
    const int colb = (lcol & 7) << 2;
    const int xrowoff = lrow * 34 + colb;

    u64 acc[4][4];
#pragma unroll
    for (int p = 0; p < 4; ++p)
#pragma unroll
        for (int i = 0; i < 4; ++i) acc[p][i] = 0ull;

#pragma unroll
    for (int t = 0; t < 32; ++t) {
        const float* xr = &x_s[xoff_s[t] + xrowoff];
        const u64*   wr = (const u64*)&w_s[t * WSTR + oc0];
        const u64 w0 = wr[0], w1 = wr[1], w2 = wr[2], w3 = wr[3];
#pragma unroll
        for (int i = 0; i < 4; ++i) {
            const u64 xx = bcast2(xr[i]);
            acc[0][i] = fma2(w0, xx, acc[0][i]);
            acc[1][i] = fma2(w1, xx, acc[1][i]);
            acc[2][i] = fma2(w2, xx, acc[2][i]);
            acc[3][i] = fma2(w3, xx, acc[3][i]);
        }
    }

    const int lbase = (oh0 + lrow) * 32 + colb;
    float* outp = g_part + (size_t)(j << 7) + oc0;
#pragma unroll
    for (int i = 0; i < 4; ++i) {
        float2 a0 = unpack2(acc[0][i]);
        float2 a1 = unpack2(acc[1][i]);
        float2 a2 = unpack2(acc[2][i]);
        float2 a3 = unpack2(acc[3][i]);
        float* po = outp + (size_t)(lbase + i) * 4608;
        *(float4*)(po)     = make_float4(a0.x, a0.y, a1.x, a1.y);
        *(float4*)(po + 4) = make_float4(a2.x, a2.y, a3.x, a3.y);
    }
}

// ---------------------------------------------------------------------------
// Kernel 2: block (128 thr, 4 warps) per l; grid = 1024.
// Warp w handles chunks j in [9w, 9w+9); lane holds oc quad lane*4..+3.
// ---------------------------------------------------------------------------
__global__ void __launch_bounds__(128)
k_quant(const float* __restrict__ bias, float* __restrict__ out) {
    const int tid  = threadIdx.x;
    const int lane = tid & 31;
    const int wid  = tid >> 5;
    const int l    = blockIdx.x;
    const int j0   = wid * 9;

    const float4* bp = (const float4*)(g_part + (size_t)l * 4608) + lane;
    // chunk j at bp[j*32]

    __shared__ float4 s[4][32];                      // [warp][lane] = oc quad

    // --- pass 1: per-warp partial totals over 9 chunks
    float4 t4 = make_float4(0.f, 0.f, 0.f, 0.f);
#pragma unroll
    for (int j = 0; j < 9; ++j) {
        float4 v = bp[(j0 + j) * 32];
        t4.x += v.x; t4.y += v.y; t4.z += v.z; t4.w += v.w;
    }
    s[wid][lane] = t4;
    __syncthreads();

    // full totals (+bias), redundantly in every warp
    float4 tot = *(const float4*)(bias + (lane << 2));
#pragma unroll
    for (int w2 = 0; w2 < 4; ++w2) {
        float4 v = s[w2][lane];
        tot.x += v.x; tot.y += v.y; tot.z += v.z; tot.w += v.w;
    }
    float mx = fmaxf(fmaxf(tot.x, tot.y), fmaxf(tot.z, tot.w));
    float mn = fminf(fminf(tot.x, tot.y), fminf(tot.z, tot.w));
#pragma unroll
    for (int sft = 16; sft > 0; sft >>= 1) {
        mx = fmaxf(mx, __shfl_xor_sync(0xffffffffu, mx, sft));
        mn = fminf(mn, __shfl_xor_sync(0xffffffffu, mn, sft));
    }

    const float sc = (mx - mn) * (1.0f / 255.0f);
    float z = -mn / sc;                              // inf/nan if sc==0
    z = fminf(fmaxf(z, 0.0f), 255.0f);               // clip (nan -> 0 via fmaxf)
    if (isnan(z)) z = 0.0f;
    const float zp  = truncf(z);
    const float rcp = 1.0f / sc;

    // --- pass 2: fake-quant own 9 chunks (L1-hot), sum (q - zp)
    float4 o = make_float4(0.f, 0.f, 0.f, 0.f);
#pragma unroll
    for (int j = 0; j < 9; ++j) {
        float4 v = bp[(j0 + j) * 32];
        o.x += fminf(fmaxf(rintf(v.x * rcp) + zp, 0.0f), 255.0f) - zp;
        o.y += fminf(fmaxf(rintf(v.y * rcp) + zp, 0.0f), 255.0f) - zp;
        o.z += fminf(fmaxf(rintf(v.z * rcp) + zp, 0.0f), 255.0f) - zp;
        o.w += fminf(fmaxf(rintf(v.w * rcp) + zp, 0.0f), 255.0f) - zp;
    }
    __syncthreads();
    s[wid][lane] = o;
    __syncthreads();

    // --- combine warps, scale, store: thread tid <-> oc = tid
    const float* sf = (const float*)s;               // [warp][oc]
    float v = sf[tid] + sf[128 + tid] + sf[256 + tid] + sf[384 + tid];
    out[(tid << 10) + l] = v * sc;
}

__global__ void k_noop() {}

// ---------------------------------------------------------------------------
extern "C" void kernel_launch(void* const* d_in, const int* in_sizes, int n_in,
                              void* d_out, int out_size) {
    const float *x = nullptr, *w = nullptr, *b = nullptr;
    for (int i = 0; i < n_in; ++i) {
        if      (in_sizes[i] == 131072) x = (const float*)d_in[i];  // 128*32*32
        else if (in_sizes[i] == 147456) w = (const float*)d_in[i];  // 128*128*9
        else if (in_sizes[i] == 128)    b = (const float*)d_in[i];
    }
    k_partials<<<dim3(16, 36), 256>>>(x, w);
    k_quant<<<1024, 128>>>(b, (float*)d_out);
    // Pad to 5 launches/call so ncu (-s 5 -c 1) lands on k_partials next call.
    k_noop<<<1, 32>>>();
    k_noop<<<1, 32>>>();
    k_noop<<<1, 32>>>();
}